// round 3
// baseline (speedup 1.0000x reference)
#include <cuda_runtime.h>
#include <cuda_bf16.h>

#define N_NODES   100000
#define N_EDGES   3200000
#define N_GRAPHS  256
#define FEAT      128

// ---------------- scratch (__device__ globals; no allocation APIs) ----------------
__device__ __align__(16) int   g_cnt[N_NODES];
__device__ __align__(16) int   g_fill[N_NODES];
__device__ __align__(16) int   g_rowstart[N_NODES];
__device__ __align__(16) int   g_bsum[512];
__device__ __align__(16) float g_dis[N_NODES];
__device__ __align__(16) int   g_col[N_EDGES];
__device__ __align__(16) float g_val[N_EDGES];
__device__ __align__(16) float g_h[(size_t)N_NODES * FEAT];   // GEMM output
__device__ __align__(16) float g_a[(size_t)N_NODES * FEAT];   // agg output / next input
__device__ __align__(16) float g_pool[N_GRAPHS * FEAT];
__device__ int g_is64;   // 1 if index tensors are int64, 0 if int32

// Load an index element `i` (element units of the true dtype).
__device__ __forceinline__ int ld_idx(const int* __restrict__ p, long long i, int is64) {
    if (is64) return (int)(((const long long*)p)[i]);
    return p[i];
}

// ---------------- dtype sniff: int64 values < 2^31 have zero odd words ----------------
__global__ void k_sniff(const int* __restrict__ ei) {
    if (threadIdx.x == 0 && blockIdx.x == 0) {
        int odd = 0;
        for (int i = 1; i < 128; i += 2) odd |= ei[i];
        g_is64 = (odd == 0) ? 1 : 0;
    }
}

// ---------------- prep ----------------
__global__ void k_zero(int n) {
    int i = blockIdx.x * blockDim.x + threadIdx.x;
    if (i < n) { g_cnt[i] = 0; g_fill[i] = 0; }
}

__global__ void k_count(const int* __restrict__ ei, int E, int n) {
    int e = blockIdx.x * blockDim.x + threadIdx.x;
    if (e >= E) return;
    int is64 = g_is64;
    int d = ld_idx(ei, (long long)E + e, is64);   // dst row
    if ((unsigned)d < (unsigned)n) atomicAdd(&g_cnt[d], 1);
}

__global__ void k_dis(int n) {
    int i = blockIdx.x * blockDim.x + threadIdx.x;
    if (i < n) g_dis[i] = rsqrtf((float)g_cnt[i] + 1.0f);   // +1 self-loop; deg > 0 always
}

__global__ void k_scan1(int n) {
    __shared__ int s[256];
    int t = threadIdx.x;
    int i = blockIdx.x * 256 + t;
    int v = (i < n) ? g_cnt[i] : 0;
    s[t] = v; __syncthreads();
    for (int off = 1; off < 256; off <<= 1) {
        int a = (t >= off) ? s[t - off] : 0;
        __syncthreads();
        s[t] += a;
        __syncthreads();
    }
    if (i < n) g_rowstart[i] = s[t] - v;
    if (t == 255) g_bsum[blockIdx.x] = s[255];
}

__global__ void k_scan2(int nb) {
    __shared__ int s[512];
    int t = threadIdx.x;
    int v = (t < nb) ? g_bsum[t] : 0;
    s[t] = v; __syncthreads();
    for (int off = 1; off < 512; off <<= 1) {
        int a = (t >= off) ? s[t - off] : 0;
        __syncthreads();
        s[t] += a;
        __syncthreads();
    }
    if (t < nb) g_bsum[t] = s[t] - v;
}

__global__ void k_scan3(int n) {
    int i = blockIdx.x * 256 + threadIdx.x;
    if (i < n) g_rowstart[i] += g_bsum[blockIdx.x];
}

__global__ void k_fillcsr(const int* __restrict__ ei, int E, int n) {
    int e = blockIdx.x * blockDim.x + threadIdx.x;
    if (e >= E) return;
    int is64 = g_is64;
    int s = ld_idx(ei, e, is64);
    int d = ld_idx(ei, (long long)E + e, is64);
    if ((unsigned)s >= (unsigned)n || (unsigned)d >= (unsigned)n) return;
    int pos = atomicAdd(&g_fill[d], 1);
    int idx = g_rowstart[d] + pos;
    g_col[idx] = s;
    g_val[idx] = g_dis[s] * g_dis[d];
}

// ---------------- GEMM: g_h[n,128] = act(A[n,128]) @ W[128,128] ----------------
// 128x128 output tile, k chunked by 32, static smem ~33 KB, 8x8 register micro-tile.
__global__ __launch_bounds__(256) void k_gemm(const float* __restrict__ Ain,
                                              const float* __restrict__ W,
                                              int n, int doRelu) {
    __shared__ float As[32][129];
    __shared__ float Ws[32][128];
    const float* A = Ain ? Ain : g_a;
    int tid = threadIdx.x;
    int row0 = blockIdx.x << 7;
    int tx = tid & 15, ty = tid >> 4;
    int m0 = ty << 3, n0 = tx << 3;

    float acc[8][8];
#pragma unroll
    for (int i = 0; i < 8; i++)
#pragma unroll
        for (int j = 0; j < 8; j++) acc[i][j] = 0.f;

    for (int k0 = 0; k0 < 128; k0 += 32) {
        for (int it = tid; it < 1024; it += 256) {
            int r = it >> 3, c4 = (it & 7) << 2;
            float4 v = make_float4(0.f, 0.f, 0.f, 0.f);
            if (row0 + r < n) v = *(const float4*)(A + (size_t)(row0 + r) * FEAT + k0 + c4);
            if (doRelu) {
                v.x = fmaxf(v.x, 0.f); v.y = fmaxf(v.y, 0.f);
                v.z = fmaxf(v.z, 0.f); v.w = fmaxf(v.w, 0.f);
            }
            As[c4 + 0][r] = v.x;
            As[c4 + 1][r] = v.y;
            As[c4 + 2][r] = v.z;
            As[c4 + 3][r] = v.w;
        }
        for (int it = tid; it < 1024; it += 256) {
            int k = it >> 5, c4 = (it & 31) << 2;
            *(float4*)(&Ws[k][c4]) = *(const float4*)(W + (size_t)(k0 + k) * FEAT + c4);
        }
        __syncthreads();

#pragma unroll
        for (int k = 0; k < 32; k++) {
            float a[8], b[8];
            float4 b0 = *(float4*)(&Ws[k][n0]);
            float4 b1 = *(float4*)(&Ws[k][n0 + 4]);
            b[0] = b0.x; b[1] = b0.y; b[2] = b0.z; b[3] = b0.w;
            b[4] = b1.x; b[5] = b1.y; b[6] = b1.z; b[7] = b1.w;
#pragma unroll
            for (int i = 0; i < 8; i++) a[i] = As[k][m0 + i];
#pragma unroll
            for (int i = 0; i < 8; i++)
#pragma unroll
                for (int j = 0; j < 8; j++) acc[i][j] = fmaf(a[i], b[j], acc[i][j]);
        }
        __syncthreads();
    }

#pragma unroll
    for (int i = 0; i < 8; i++) {
        int r = row0 + m0 + i;
        if (r < n) {
            *(float4*)(g_h + (size_t)r * FEAT + n0) =
                make_float4(acc[i][0], acc[i][1], acc[i][2], acc[i][3]);
            *(float4*)(g_h + (size_t)r * FEAT + n0 + 4) =
                make_float4(acc[i][4], acc[i][5], acc[i][6], acc[i][7]);
        }
    }
}

// ---------------- aggregation: g_a[i] = b + dis[i]^2*g_h[i] + sum val[e]*g_h[col[e]] ----------------
__global__ void k_agg(const float* __restrict__ bias, int n) {
    int w = (blockIdx.x * blockDim.x + threadIdx.x) >> 5;
    int lane = threadIdx.x & 31;
    if (w >= n) return;
    int start = g_rowstart[w];
    int m = g_cnt[w];
    float d = g_dis[w];
    float dd = d * d;
    float4 hv = *((const float4*)(g_h + (size_t)w * FEAT) + lane);
    float4 bv = __ldg((const float4*)bias + lane);
    float4 acc;
    acc.x = bv.x + hv.x * dd;
    acc.y = bv.y + hv.y * dd;
    acc.z = bv.z + hv.z * dd;
    acc.w = bv.w + hv.w * dd;
    for (int j = 0; j < m; j++) {
        int   c = g_col[start + j];
        float v = g_val[start + j];
        float4 hm = *((const float4*)(g_h + (size_t)c * FEAT) + lane);
        acc.x = fmaf(hm.x, v, acc.x);
        acc.y = fmaf(hm.y, v, acc.y);
        acc.z = fmaf(hm.z, v, acc.z);
        acc.w = fmaf(hm.w, v, acc.w);
    }
    ((float4*)(g_a + (size_t)w * FEAT))[lane] = acc;
}

// ---------------- mean pool over sorted batch (relu on read) ----------------
__global__ void k_pool(const int* __restrict__ batch, int n) {
    int g = blockIdx.x;
    int f = threadIdx.x;
    int is64 = g_is64;
    int lo = 0, hi = n;
    while (lo < hi) { int mid = (lo + hi) >> 1; if (ld_idx(batch, mid, is64) < g) lo = mid + 1; else hi = mid; }
    int s = lo;
    hi = n;
    while (lo < hi) { int mid = (lo + hi) >> 1; if (ld_idx(batch, mid, is64) <= g) lo = mid + 1; else hi = mid; }
    int e = lo;
    float acc = 0.f;
    for (int i = s; i < e; i++) acc += fmaxf(g_a[(size_t)i * FEAT + f], 0.f);
    int c = e - s;
    g_pool[g * FEAT + f] = acc / (float)(c > 0 ? c : 1);
}

// ---------------- MLP head ----------------
__global__ void k_mlp(const float* __restrict__ w1, const float* __restrict__ b1,
                      const float* __restrict__ w2, const float* __restrict__ b2,
                      float* __restrict__ out) {
    int g = blockIdx.x;
    int t = threadIdx.x;  // 128
    __shared__ float gs[128];
    __shared__ float ts[128];
    gs[t] = g_pool[g * FEAT + t];
    __syncthreads();
    float acc = b1[t];
#pragma unroll 8
    for (int k = 0; k < 128; k++) acc = fmaf(gs[k], w1[k * 128 + t], acc);
    ts[t] = fmaxf(acc, 0.f);
    __syncthreads();
    if (t < 10) {
        float o = b2[t];
#pragma unroll 8
        for (int j = 0; j < 128; j++) o = fmaf(ts[j], w2[j * 10 + t], o);
        out[g * 10 + t] = o;
    }
}

// ---------------- launcher ----------------
extern "C" void kernel_launch(void* const* d_in, const int* in_sizes, int n_in,
                              void* d_out, int out_size) {
    const float* x     = (const float*)d_in[0];
    const int*   ei    = (const int*)d_in[1];     // [2,E] int32 (or int64, sniffed)
    const int*   batch = (const int*)d_in[2];
    const float* W1 = (const float*)d_in[3];  const float* b1 = (const float*)d_in[4];
    const float* W2 = (const float*)d_in[5];  const float* b2 = (const float*)d_in[6];
    const float* W3 = (const float*)d_in[7];  const float* b3 = (const float*)d_in[8];
    const float* l1w = (const float*)d_in[9];  const float* l1b = (const float*)d_in[10];
    const float* l2w = (const float*)d_in[11]; const float* l2b = (const float*)d_in[12];
    float* out = (float*)d_out;

    int n = in_sizes[0] / FEAT;   // 100000
    int E = in_sizes[1] / 2;      // 3200000

    int nb = (n + 255) / 256;
    int eb = (E + 255) / 256;
    int gb = (n + 127) / 128;
    long long athreads = (long long)n * 32;
    int ab = (int)((athreads + 255) / 256);

    k_sniff  <<<1, 32>>>(ei);
    k_zero   <<<nb, 256>>>(n);
    k_count  <<<eb, 256>>>(ei, E, n);
    k_dis    <<<nb, 256>>>(n);
    k_scan1  <<<nb, 256>>>(n);
    k_scan2  <<<1, 512>>>(nb);
    k_scan3  <<<nb, 256>>>(n);
    k_fillcsr<<<eb, 256>>>(ei, E, n);

    k_gemm<<<gb, 256>>>(x, W1, n, 0);
    k_agg <<<ab, 256>>>(b1, n);
    k_gemm<<<gb, 256>>>(nullptr, W2, n, 1);
    k_agg <<<ab, 256>>>(b2, n);
    k_gemm<<<gb, 256>>>(nullptr, W3, n, 1);
    k_agg <<<ab, 256>>>(b3, n);

    k_pool<<<N_GRAPHS, 128>>>(batch, n);
    k_mlp <<<N_GRAPHS, 128>>>(l1w, l1b, l2w, l2b, out);
}

// round 4
// speedup vs baseline: 1.6691x; 1.6691x over previous
#include <cuda_runtime.h>
#include <cuda_bf16.h>

#define N_NODES   100000
#define N_EDGES   3200000
#define N_GRAPHS  256
#define FEAT      128

// ---------------- scratch (__device__ globals) ----------------
__device__ __align__(16) int   g_cnt[N_NODES];
__device__ __align__(16) int   g_fill[N_NODES];
__device__ __align__(16) int   g_rowstart[N_NODES];
__device__ __align__(16) int   g_bsum[512];
__device__ __align__(16) float g_dis[N_NODES];
__device__ __align__(16) int2  g_cv[N_EDGES];                       // (col, val-as-int)
__device__ __align__(16) __nv_bfloat16 g_hb[(size_t)N_NODES * FEAT]; // GEMM output (bf16)
__device__ __align__(16) float g_a[(size_t)N_NODES * FEAT];          // agg output (post-relu)
__device__ __align__(16) float g_pool[N_GRAPHS * FEAT];
__device__ int g_is64;

__device__ __forceinline__ int ld_idx(const int* __restrict__ p, long long i, int is64) {
    if (is64) return (int)(((const long long*)p)[i]);
    return p[i];
}

// ---------------- dtype sniff ----------------
__global__ void k_sniff(const int* __restrict__ ei) {
    if (threadIdx.x == 0 && blockIdx.x == 0) {
        int odd = 0;
        for (int i = 1; i < 128; i += 2) odd |= ei[i];
        g_is64 = (odd == 0) ? 1 : 0;
    }
}

// ---------------- prep ----------------
__global__ void k_zero(int n) {
    int i = blockIdx.x * blockDim.x + threadIdx.x;
    if (i < n) { g_cnt[i] = 0; g_fill[i] = 0; }
}

__global__ void k_count(const int* __restrict__ ei, int E, int n) {
    int e = blockIdx.x * blockDim.x + threadIdx.x;
    if (e >= E) return;
    int d = ld_idx(ei, (long long)E + e, g_is64);
    if ((unsigned)d < (unsigned)n) atomicAdd(&g_cnt[d], 1);
}

__global__ void k_dis(int n) {
    int i = blockIdx.x * blockDim.x + threadIdx.x;
    if (i < n) g_dis[i] = rsqrtf((float)g_cnt[i] + 1.0f);
}

__global__ void k_scan1(int n) {
    __shared__ int s[256];
    int t = threadIdx.x;
    int i = blockIdx.x * 256 + t;
    int v = (i < n) ? g_cnt[i] : 0;
    s[t] = v; __syncthreads();
    for (int off = 1; off < 256; off <<= 1) {
        int a = (t >= off) ? s[t - off] : 0;
        __syncthreads();
        s[t] += a;
        __syncthreads();
    }
    if (i < n) g_rowstart[i] = s[t] - v;
    if (t == 255) g_bsum[blockIdx.x] = s[255];
}

__global__ void k_scan2(int nb) {
    __shared__ int s[512];
    int t = threadIdx.x;
    int v = (t < nb) ? g_bsum[t] : 0;
    s[t] = v; __syncthreads();
    for (int off = 1; off < 512; off <<= 1) {
        int a = (t >= off) ? s[t - off] : 0;
        __syncthreads();
        s[t] += a;
        __syncthreads();
    }
    if (t < nb) g_bsum[t] = s[t] - v;
}

__global__ void k_scan3(int n) {
    int i = blockIdx.x * 256 + threadIdx.x;
    if (i < n) g_rowstart[i] += g_bsum[blockIdx.x];
}

__global__ void k_fillcsr(const int* __restrict__ ei, int E, int n) {
    int e = blockIdx.x * blockDim.x + threadIdx.x;
    if (e >= E) return;
    int is64 = g_is64;
    int s = ld_idx(ei, e, is64);
    int d = ld_idx(ei, (long long)E + e, is64);
    if ((unsigned)s >= (unsigned)n || (unsigned)d >= (unsigned)n) return;
    int pos = atomicAdd(&g_fill[d], 1);
    float v = g_dis[s] * g_dis[d];
    g_cv[g_rowstart[d] + pos] = make_int2(s, __float_as_int(v));
}

// ---------------- GEMM: g_hb[n,128] = A[n,128] @ W[128,128]  (bf16 output) ----------------
__global__ __launch_bounds__(256) void k_gemm(const float* __restrict__ Ain,
                                              const float* __restrict__ W, int n) {
    __shared__ float As[32][129];
    __shared__ float Ws[32][128];
    const float* A = Ain ? Ain : g_a;
    int tid = threadIdx.x;
    int row0 = blockIdx.x << 7;
    int tx = tid & 15, ty = tid >> 4;
    int m0 = ty << 3, n0 = tx << 3;

    float acc[8][8];
#pragma unroll
    for (int i = 0; i < 8; i++)
#pragma unroll
        for (int j = 0; j < 8; j++) acc[i][j] = 0.f;

    for (int k0 = 0; k0 < 128; k0 += 32) {
        for (int it = tid; it < 1024; it += 256) {
            int r = it >> 3, c4 = (it & 7) << 2;
            float4 v = make_float4(0.f, 0.f, 0.f, 0.f);
            if (row0 + r < n) v = *(const float4*)(A + (size_t)(row0 + r) * FEAT + k0 + c4);
            As[c4 + 0][r] = v.x;
            As[c4 + 1][r] = v.y;
            As[c4 + 2][r] = v.z;
            As[c4 + 3][r] = v.w;
        }
        for (int it = tid; it < 1024; it += 256) {
            int k = it >> 5, c4 = (it & 31) << 2;
            *(float4*)(&Ws[k][c4]) = *(const float4*)(W + (size_t)(k0 + k) * FEAT + c4);
        }
        __syncthreads();

#pragma unroll
        for (int k = 0; k < 32; k++) {
            float a[8], b[8];
            float4 b0 = *(float4*)(&Ws[k][n0]);
            float4 b1 = *(float4*)(&Ws[k][n0 + 4]);
            b[0] = b0.x; b[1] = b0.y; b[2] = b0.z; b[3] = b0.w;
            b[4] = b1.x; b[5] = b1.y; b[6] = b1.z; b[7] = b1.w;
#pragma unroll
            for (int i = 0; i < 8; i++) a[i] = As[k][m0 + i];
#pragma unroll
            for (int i = 0; i < 8; i++)
#pragma unroll
                for (int j = 0; j < 8; j++) acc[i][j] = fmaf(a[i], b[j], acc[i][j]);
        }
        __syncthreads();
    }

#pragma unroll
    for (int i = 0; i < 8; i++) {
        int r = row0 + m0 + i;
        if (r < n) {
            __nv_bfloat162 o0 = __floats2bfloat162_rn(acc[i][0], acc[i][1]);
            __nv_bfloat162 o1 = __floats2bfloat162_rn(acc[i][2], acc[i][3]);
            __nv_bfloat162 o2 = __floats2bfloat162_rn(acc[i][4], acc[i][5]);
            __nv_bfloat162 o3 = __floats2bfloat162_rn(acc[i][6], acc[i][7]);
            uint4 st;
            st.x = *(unsigned*)&o0; st.y = *(unsigned*)&o1;
            st.z = *(unsigned*)&o2; st.w = *(unsigned*)&o3;
            *(uint4*)(g_hb + (size_t)r * FEAT + n0) = st;
        }
    }
}

// ---------------- aggregation (bf16 gathers, fp32 accum, relu on write) ----------------
// g_a[i] = relu( b + dis[i]^2*hb[i] + sum_e val[e]*hb[col[e]] )
__global__ void k_agg(const float* __restrict__ bias, int n) {
    int w = (blockIdx.x * blockDim.x + threadIdx.x) >> 5;
    int lane = threadIdx.x & 31;
    if (w >= n) return;
    int start = g_rowstart[w];
    int m = g_cnt[w];
    float d = g_dis[w];
    float dd = d * d;

    uint2 sv = *((const uint2*)(g_hb + (size_t)w * FEAT) + lane);
    float2 s0 = __bfloat1622float2(*(const __nv_bfloat162*)&sv.x);
    float2 s1 = __bfloat1622float2(*(const __nv_bfloat162*)&sv.y);
    float4 bv = __ldg((const float4*)bias + lane);
    float4 acc;
    acc.x = bv.x + s0.x * dd;
    acc.y = bv.y + s0.y * dd;
    acc.z = bv.z + s1.x * dd;
    acc.w = bv.w + s1.y * dd;

    for (int j = 0; j < m; j++) {
        int2 cv = g_cv[start + j];
        float v = __int_as_float(cv.y);
        uint2 hm = *((const uint2*)(g_hb + (size_t)cv.x * FEAT) + lane);
        float2 f0 = __bfloat1622float2(*(const __nv_bfloat162*)&hm.x);
        float2 f1 = __bfloat1622float2(*(const __nv_bfloat162*)&hm.y);
        acc.x = fmaf(f0.x, v, acc.x);
        acc.y = fmaf(f0.y, v, acc.y);
        acc.z = fmaf(f1.x, v, acc.z);
        acc.w = fmaf(f1.y, v, acc.w);
    }
    acc.x = fmaxf(acc.x, 0.f);
    acc.y = fmaxf(acc.y, 0.f);
    acc.z = fmaxf(acc.z, 0.f);
    acc.w = fmaxf(acc.w, 0.f);
    ((float4*)(g_a + (size_t)w * FEAT))[lane] = acc;
}

// ---------------- mean pool over sorted batch (inputs already relu'd) ----------------
__global__ void k_pool(const int* __restrict__ batch, int n) {
    int g = blockIdx.x;
    int f = threadIdx.x;
    int is64 = g_is64;
    int lo = 0, hi = n;
    while (lo < hi) { int mid = (lo + hi) >> 1; if (ld_idx(batch, mid, is64) < g) lo = mid + 1; else hi = mid; }
    int s = lo;
    hi = n;
    while (lo < hi) { int mid = (lo + hi) >> 1; if (ld_idx(batch, mid, is64) <= g) lo = mid + 1; else hi = mid; }
    int e = lo;
    float acc = 0.f;
    for (int i = s; i < e; i++) acc += g_a[(size_t)i * FEAT + f];
    int c = e - s;
    g_pool[g * FEAT + f] = acc / (float)(c > 0 ? c : 1);
}

// ---------------- MLP head ----------------
__global__ void k_mlp(const float* __restrict__ w1, const float* __restrict__ b1,
                      const float* __restrict__ w2, const float* __restrict__ b2,
                      float* __restrict__ out) {
    int g = blockIdx.x;
    int t = threadIdx.x;  // 128
    __shared__ float gs[128];
    __shared__ float ts[128];
    gs[t] = g_pool[g * FEAT + t];
    __syncthreads();
    float acc = b1[t];
#pragma unroll 8
    for (int k = 0; k < 128; k++) acc = fmaf(gs[k], w1[k * 128 + t], acc);
    ts[t] = fmaxf(acc, 0.f);
    __syncthreads();
    if (t < 10) {
        float o = b2[t];
#pragma unroll 8
        for (int j = 0; j < 128; j++) o = fmaf(ts[j], w2[j * 10 + t], o);
        out[g * 10 + t] = o;
    }
}

// ---------------- launcher ----------------
extern "C" void kernel_launch(void* const* d_in, const int* in_sizes, int n_in,
                              void* d_out, int out_size) {
    const float* x     = (const float*)d_in[0];
    const int*   ei    = (const int*)d_in[1];
    const int*   batch = (const int*)d_in[2];
    const float* W1 = (const float*)d_in[3];  const float* b1 = (const float*)d_in[4];
    const float* W2 = (const float*)d_in[5];  const float* b2 = (const float*)d_in[6];
    const float* W3 = (const float*)d_in[7];  const float* b3 = (const float*)d_in[8];
    const float* l1w = (const float*)d_in[9];  const float* l1b = (const float*)d_in[10];
    const float* l2w = (const float*)d_in[11]; const float* l2b = (const float*)d_in[12];
    float* out = (float*)d_out;

    int n = in_sizes[0] / FEAT;   // 100000
    int E = in_sizes[1] / 2;      // 3200000

    int nb = (n + 255) / 256;
    int eb = (E + 255) / 256;
    int gb = (n + 127) / 128;
    long long athreads = (long long)n * 32;
    int ab = (int)((athreads + 255) / 256);

    k_sniff  <<<1, 32>>>(ei);
    k_zero   <<<nb, 256>>>(n);
    k_count  <<<eb, 256>>>(ei, E, n);
    k_dis    <<<nb, 256>>>(n);
    k_scan1  <<<nb, 256>>>(n);
    k_scan2  <<<1, 512>>>(nb);
    k_scan3  <<<nb, 256>>>(n);
    k_fillcsr<<<eb, 256>>>(ei, E, n);

    k_gemm<<<gb, 256>>>(x, W1, n);
    k_agg <<<ab, 256>>>(b1, n);
    k_gemm<<<gb, 256>>>(nullptr, W2, n);
    k_agg <<<ab, 256>>>(b2, n);
    k_gemm<<<gb, 256>>>(nullptr, W3, n);
    k_agg <<<ab, 256>>>(b3, n);

    k_pool<<<N_GRAPHS, 128>>>(batch, n);
    k_mlp <<<N_GRAPHS, 128>>>(l1w, l1b, l2w, l2b, out);
}